// round 12
// baseline (speedup 1.0000x reference)
#include <cuda_runtime.h>
#include <cuda_fp16.h>
#include <math.h>

#define Bq 2
#define Dq 256
#define Hq 8
#define Tq 128
#define Fq 64
#define Cq 512
#define TEq 512
#define NDIST 255   // pd in [-127,127]
#define NKQ 8       // tp K-slices

// ---------------- scratch (device globals; no allocation allowed) ----------
__device__ float  g_tpp[NKQ * Bq * Tq * Cq];       // tp partial sums [kq][bt][c]
__device__ float  g_lut[NDIST * Cq];               // dist-emb LUT (255,C)
__device__ __half g_Bn [Cq * Cq];                  // w_out fp16, transposed [n][k]
__device__ __half g_A  [(size_t)Bq * Tq * Tq * Cq]; // fp16(silu(emb))  33 MB

#define TPP_SLICE (Bq * Tq * Cq)                   // 131072 floats per kq slice

// ---------------- fused-kernel smem layout (in halves) ----------------------
// Phase 1: A stages [0,1] at 0 / STAGE_H; B stages at 2*STAGE_H / 3*STAGE_H.
// K-chunk 64, row stride 72 halves (64 + 8 pad -> conflict-free ldsm).
#define STAGE_H   (128 * 72)                 // 9216 halves per stage per operand
#define B_BASE_H  (2 * STAGE_H)              // 18432
#define RS_H      (4 * STAGE_H)              // 36864
#define RS_STRIDE 136                        // halves
#define SBO_BYTE  ((RS_H + 128 * RS_STRIDE) * 2)   // 108544
#define SMEM_BYTES (SBO_BYTE + 512)                // 109056
#define QBUF_H    STAGE_H                    // qk buffer = 128 x 72 halves

// ---------------- helpers ----------------------------------------------------
__device__ __forceinline__ void mma16(float c[4],
                                      const unsigned a[4],
                                      unsigned b0, unsigned b1) {
    asm volatile(
        "mma.sync.aligned.m16n8k16.row.col.f32.f16.f16.f32 "
        "{%0,%1,%2,%3}, {%4,%5,%6,%7}, {%8,%9}, {%0,%1,%2,%3};"
        : "+f"(c[0]), "+f"(c[1]), "+f"(c[2]), "+f"(c[3])
        : "r"(a[0]), "r"(a[1]), "r"(a[2]), "r"(a[3]), "r"(b0), "r"(b1));
}

__device__ __forceinline__ void ldsm4(unsigned r[4], unsigned addr) {
    asm volatile("ldmatrix.sync.aligned.m8n8.x4.shared.b16 {%0,%1,%2,%3}, [%4];"
                 : "=r"(r[0]), "=r"(r[1]), "=r"(r[2]), "=r"(r[3]) : "r"(addr));
}

__device__ __forceinline__ float silu(float x) {
    return x / (1.0f + __expf(-x));
}

__device__ __forceinline__ void cpa16(void* dst, const void* src) {
    unsigned d = (unsigned)__cvta_generic_to_shared(dst);
    asm volatile("cp.async.cg.shared.global [%0], [%1], 16;" :: "r"(d), "l"(src) : "memory");
}

// ---------------- kernel 1: merged prologue ---------------------------------
// blocks [0,255): dist LUT
// blocks [255,319): w_out -> fp16 transposed [n][k] via smem 64x64 tiles
// blocks [319, 319+2048): time_proj partials, block = (bt, kq), 64-k slice
__global__ __launch_bounds__(512) void prep_kernel(const float* __restrict__ w_dist,
                                                   const float* __restrict__ b_dist,
                                                   const float* __restrict__ w_out,
                                                   const float* __restrict__ temb,
                                                   const float* __restrict__ w_time,
                                                   const float* __restrict__ b_time) {
    int blk = blockIdx.x;
    int tid = threadIdx.x;
    if (blk < NDIST) {
        int didx = blk;
        float d  = (float)(didx - (Tq - 1));
        float e0 = log1pf(fmaxf(d, 0.0f));
        float e1 = log1pf(fmaxf(-d, 0.0f));
        float e2 = (didx == (Tq - 1)) ? 1.0f : 0.0f;
        g_lut[didx * Cq + tid] = e0 * w_dist[0 * Cq + tid]
                               + e1 * w_dist[1 * Cq + tid]
                               + e2 * w_dist[2 * Cq + tid]
                               + b_dist[tid];
    } else if (blk < NDIST + 64) {
        __shared__ __half ts[64][65];
        int blk2 = blk - NDIST;               // 0..63
        int k0 = (blk2 >> 3) * 64, n0 = (blk2 & 7) * 64;
        int cl = tid & 63, rbase = tid >> 6;  // 8 rows/pass
        #pragma unroll
        for (int r = 0; r < 8; ++r) {
            int kl = r * 8 + rbase;
            ts[kl][cl] = __float2half(w_out[(size_t)(k0 + kl) * Cq + n0 + cl]);
        }
        __syncthreads();
        #pragma unroll
        for (int r = 0; r < 8; ++r) {
            int nl = r * 8 + rbase;
            g_Bn[(size_t)(n0 + nl) * Cq + k0 + cl] = ts[cl][nl];
        }
    } else {
        __shared__ float st[64];
        int idx = blk - NDIST - 64;           // 0..2047
        int bt = idx >> 3, kq = idx & 7;
        int c  = tid;
        if (tid < 64) st[tid] = temb[(size_t)bt * TEq + kq * 64 + tid];
        __syncthreads();
        float acc = (kq == 0) ? b_time[c] : 0.0f;
        const float* wp = w_time + (size_t)(kq * 64) * Cq + c;
        #pragma unroll 16
        for (int k = 0; k < 64; ++k)
            acc += st[k] * wp[(size_t)k * Cq];
        g_tpp[(size_t)(kq * (Bq * Tq) + bt) * Cq + c] = acc;
    }
}

// ---------------- kernel 2: A = fp16(silu(sum_kq tpp + lut[pd]))  -----------
__global__ __launch_bounds__(256) void act_kernel(const int* __restrict__ pd) {
    int idx    = blockIdx.x * 256 + threadIdx.x;
    int k8     = (idx & 63) * 8;           // 0..504
    int rowidx = idx >> 6;                 // 0..32767  (= bt*128 + s)
    int bt     = rowidx >> 7;
    int didx   = pd[rowidx] + (Tq - 1);
    const float* lp = g_lut + (size_t)didx * Cq + k8;
    const float* tp = g_tpp + (size_t)bt   * Cq + k8;
    float4 t0 = *(const float4*)tp;
    float4 t1 = *(const float4*)(tp + 4);
    #pragma unroll
    for (int kq = 1; kq < NKQ; ++kq) {
        const float* tq = tp + (size_t)kq * TPP_SLICE;
        float4 p0 = *(const float4*)tq;
        float4 p1 = *(const float4*)(tq + 4);
        t0.x += p0.x; t0.y += p0.y; t0.z += p0.z; t0.w += p0.w;
        t1.x += p1.x; t1.y += p1.y; t1.z += p1.z; t1.w += p1.w;
    }
    float4 l0 = *(const float4*)lp;
    float4 l1 = *(const float4*)(lp + 4);
    union { uint4 u; __half2 h[4]; } o;
    o.h[0] = __floats2half2_rn(silu(t0.x + l0.x), silu(t0.y + l0.y));
    o.h[1] = __floats2half2_rn(silu(t0.z + l0.z), silu(t0.w + l0.w));
    o.h[2] = __floats2half2_rn(silu(t1.x + l1.x), silu(t1.y + l1.y));
    o.h[3] = __floats2half2_rn(silu(t1.z + l1.z), silu(t1.w + l1.w));
    *(uint4*)(g_A + (size_t)rowidx * Cq + k8) = o.u;
}

// ---------------- kernel 3: FUSED  R-tile GEMM + einsum (fp16 MMA) ----------
// block = (bn: 128-col chunk of C = 2 heads, bt: one (b,t) pair).
// Phase 1: Rs[128 s][128 f'] = A(bt) @ Bn(bn)^T + bias   (smem, fp16)
//          K-chunk 64, 2-stage double buffer, 8 iterations.
// Phase 2: for dchunk(2) x hh(2): out[d,s] = qk[d,f] . Rs[s, hh*64+f]
__global__ __launch_bounds__(512, 2) void fused_tc(const float* __restrict__ b_out,
                                                   const float* __restrict__ qk,
                                                   float* __restrict__ out) {
    extern __shared__ __half sm[];
    __half* Rs  = sm + RS_H;
    float*  sbo = (float*)((char*)sm + SBO_BYTE);

    int tid = threadIdx.x;
    int bn = blockIdx.x;           // 0..3
    int bt = blockIdx.y;           // 0..255
    if (tid < 128) sbo[tid] = b_out[bn * 128 + tid];

    // ---------------- phase 1 ------------------------------------------------
    // cp geometry: 128 rows x 8 segs (16B) per operand -> 2 per thread each
    int crow = tid >> 3;           // 0..63 (+64 for r=1)
    int cseg = tid & 7;            // 0..7
    const __half* Asrc = g_A  + (size_t)(bt * 128) * Cq + cseg * 8;
    const __half* Bsrc = g_Bn + (size_t)(bn * 128) * Cq + cseg * 8;

    #define ISSUE(stage, kk)                                                      \
        { _Pragma("unroll")                                                       \
          for (int r = 0; r < 2; ++r) {                                           \
              cpa16(sm + (stage) * STAGE_H + (crow + 64 * r) * 72 + cseg * 8,     \
                    Asrc + (size_t)(kk) + (size_t)(crow + 64 * r) * Cq);          \
              cpa16(sm + B_BASE_H + (stage) * STAGE_H                             \
                       + (crow + 64 * r) * 72 + cseg * 8,                         \
                    Bsrc + (size_t)(kk) + (size_t)(crow + 64 * r) * Cq);          \
          }                                                                       \
          asm volatile("cp.async.commit_group;" ::: "memory"); }

    ISSUE(0, 0)
    ISSUE(1, 64)
    asm volatile("cp.async.wait_group 1;" ::: "memory");
    __syncthreads();

    int lane = tid & 31, warp = tid >> 5;   // 16 warps
    int g = lane >> 2, tig = lane & 3;
    int wm = warp & 3, wn = warp >> 2;
    int mbase = wm * 32, nbase = wn * 32;

    unsigned aBase = (unsigned)__cvta_generic_to_shared(sm);
    unsigned bBase = (unsigned)__cvta_generic_to_shared(sm + B_BASE_H);
    unsigned rBase = (unsigned)__cvta_generic_to_shared(Rs);
    int rowA   = lane & 15;
    int colA16 = (lane >> 4) * 16;          // bytes
    int rowB   = (lane & 7) | ((lane & 16) >> 1);
    int colB16 = ((lane >> 3) & 1) * 16;    // bytes
    unsigned aAddr[2], bAddr[2];
    #pragma unroll
    for (int mt = 0; mt < 2; ++mt)
        aAddr[mt] = aBase + (mbase + mt * 16 + rowA) * 144 + colA16;
    #pragma unroll
    for (int p = 0; p < 2; ++p)
        bAddr[p] = bBase + (nbase + p * 16 + rowB) * 144 + colB16;

    {
        float acc[2][4][4] = {};
        for (int i = 0; i < 8; ++i) {
            int cur = i & 1;
            unsigned bufo = (unsigned)cur * (STAGE_H * 2);
            #pragma unroll
            for (int ks = 0; ks < 4; ++ks) {
                unsigned off = bufo + ks * 32;
                unsigned a0[4], a1[4], bfr[4];
                ldsm4(a0, aAddr[0] + off);
                ldsm4(a1, aAddr[1] + off);
                #pragma unroll
                for (int p = 0; p < 2; ++p) {
                    ldsm4(bfr, bAddr[p] + off);
                    mma16(acc[0][2 * p],     a0, bfr[0], bfr[1]);
                    mma16(acc[0][2 * p + 1], a0, bfr[2], bfr[3]);
                    mma16(acc[1][2 * p],     a1, bfr[0], bfr[1]);
                    mma16(acc[1][2 * p + 1], a1, bfr[2], bfr[3]);
                }
            }
            if (i < 7) {
                __syncthreads();                       // all done reading cur
                if (i + 2 < 8) {
                    ISSUE(cur, (i + 2) * 64)           // refill cur
                    asm volatile("cp.async.wait_group 1;" ::: "memory");
                } else {
                    asm volatile("cp.async.wait_group 0;" ::: "memory");
                }
                __syncthreads();                       // chunk i+1 visible
            }
        }
        #undef ISSUE

        // phase-1 epilogue: Rs[s][f'] = fp16(acc + bias)
        #pragma unroll
        for (int mt = 0; mt < 2; ++mt) {
            int r0 = mbase + mt * 16 + g;
            #pragma unroll
            for (int nt = 0; nt < 4; ++nt) {
                int nl = nbase + nt * 8 + 2 * tig;
                *(__half2*)&Rs[r0 * RS_STRIDE + nl] =
                    __floats2half2_rn(acc[mt][nt][0] + sbo[nl],
                                      acc[mt][nt][1] + sbo[nl + 1]);
                *(__half2*)&Rs[(r0 + 8) * RS_STRIDE + nl] =
                    __floats2half2_rn(acc[mt][nt][2] + sbo[nl],
                                      acc[mt][nt][3] + sbo[nl + 1]);
            }
        }
    }
    __syncthreads();   // Rs complete; pipeline smem free for qk buffers

    // ---------------- phase 2 ------------------------------------------------
    int b = bt >> 7, t = bt & 127;
    const size_t dstr = (size_t)Hq * Tq * Fq;   // 65536
    const size_t ostr = (size_t)Hq * Tq * Tq;   // 131072
    __half* Qs = sm;                            // [2][128][72] halves

    unsigned aAddr2[2], bAddr2[2];
    #pragma unroll
    for (int mt = 0; mt < 2; ++mt)
        aAddr2[mt] = aBase + (mbase + mt * 16 + rowA) * 144 + colA16;
    #pragma unroll
    for (int p = 0; p < 2; ++p)
        bAddr2[p] = rBase + (nbase + p * 16 + rowB) * 272 + colB16;

    // prologue: load qk tile for iter 0 (dchunk 0, head 2*bn)
    float4 qv[4];
    {
        const float* qp = qk + ((((size_t)b * Dq) * Hq + 2 * bn) * Tq + t) * Fq;
        #pragma unroll
        for (int r = 0; r < 4; ++r) {
            int idx = tid + r * 512;
            int row = idx >> 4, f4 = (idx & 15) * 4;
            qv[r] = *(const float4*)(qp + (size_t)row * dstr + f4);
        }
        #pragma unroll
        for (int r = 0; r < 4; ++r) {
            int idx = tid + r * 512;
            int row = idx >> 4, f4 = (idx & 15) * 4;
            union { uint2 u; __half2 h[2]; } o;
            o.h[0] = __floats2half2_rn(qv[r].x, qv[r].y);
            o.h[1] = __floats2half2_rn(qv[r].z, qv[r].w);
            *(uint2*)&Qs[row * 72 + f4] = o.u;
        }
    }
    __syncthreads();

    #pragma unroll
    for (int iter = 0; iter < 4; ++iter) {
        int cur = iter & 1;
        int dchunk = iter >> 1, hh = iter & 1;
        if (iter < 3) {
            int ni = iter + 1;
            const float* qp = qk + ((((size_t)b * Dq + (ni >> 1) * 128) * Hq
                                     + 2 * bn + (ni & 1)) * Tq + t) * Fq;
            #pragma unroll
            for (int r = 0; r < 4; ++r) {
                int idx = tid + r * 512;
                int row = idx >> 4, f4 = (idx & 15) * 4;
                qv[r] = *(const float4*)(qp + (size_t)row * dstr + f4);
            }
        }
        float acc2[2][4][4] = {};
        unsigned qoff = (unsigned)cur * (QBUF_H * 2);
        unsigned roff = (unsigned)hh * 128;          // hh*64 halves (bytes)
        #pragma unroll
        for (int ks = 0; ks < 4; ++ks) {
            unsigned off = ks * 32;
            unsigned a0[4], a1[4], bfr[4];
            ldsm4(a0, aAddr2[0] + qoff + off);
            ldsm4(a1, aAddr2[1] + qoff + off);
            #pragma unroll
            for (int p = 0; p < 2; ++p) {
                ldsm4(bfr, bAddr2[p] + roff + off);
                mma16(acc2[0][2 * p],     a0, bfr[0], bfr[1]);
                mma16(acc2[0][2 * p + 1], a0, bfr[2], bfr[3]);
                mma16(acc2[1][2 * p],     a1, bfr[0], bfr[1]);
                mma16(acc2[1][2 * p + 1], a1, bfr[2], bfr[3]);
            }
        }
        float* ob = out + ((((size_t)b * Dq + dchunk * 128) * Hq
                            + 2 * bn + hh) * Tq + t) * Tq;
        #pragma unroll
        for (int mt = 0; mt < 2; ++mt) {
            int r0 = mbase + mt * 16 + g;
            #pragma unroll
            for (int nt = 0; nt < 4; ++nt) {
                int nl = nbase + nt * 8 + 2 * tig;
                *(float2*)(ob + (size_t)r0 * ostr + nl) =
                    make_float2(acc2[mt][nt][0], acc2[mt][nt][1]);
                *(float2*)(ob + (size_t)(r0 + 8) * ostr + nl) =
                    make_float2(acc2[mt][nt][2], acc2[mt][nt][3]);
            }
        }
        if (iter < 3) {
            #pragma unroll
            for (int r = 0; r < 4; ++r) {
                int idx = tid + r * 512;
                int row = idx >> 4, f4 = (idx & 15) * 4;
                union { uint2 u; __half2 h[2]; } o;
                o.h[0] = __floats2half2_rn(qv[r].x, qv[r].y);
                o.h[1] = __floats2half2_rn(qv[r].z, qv[r].w);
                *(uint2*)&Qs[(cur ^ 1) * QBUF_H + row * 72 + f4] = o.u;
            }
            __syncthreads();
        }
    }
}

// ---------------------------------------------------------------------------
extern "C" void kernel_launch(void* const* d_in, const int* in_sizes, int n_in,
                              void* d_out, int out_size) {
    const float* qk     = (const float*)d_in[0];
    const float* temb   = (const float*)d_in[1];
    const int*   pd     = (const int*)  d_in[2];
    const float* w_dist = (const float*)d_in[3];
    const float* b_dist = (const float*)d_in[4];
    const float* w_time = (const float*)d_in[5];
    const float* b_time = (const float*)d_in[6];
    const float* w_out  = (const float*)d_in[7];
    const float* b_out  = (const float*)d_in[8];
    float* out = (float*)d_out;

    static int smem_set = 0;
    if (!smem_set) {
        cudaFuncSetAttribute(fused_tc, cudaFuncAttributeMaxDynamicSharedMemorySize,
                             SMEM_BYTES);
        smem_set = 1;
    }

    prep_kernel<<<NDIST + 64 + NKQ * Bq * Tq, 512>>>(w_dist, b_dist, w_out,
                                                     temb, w_time, b_time);
    act_kernel<<<(Bq * Tq * Tq * Cq / 8) / 256, 256>>>(pd);
    dim3 gF(Cq / 128, (Bq * Tq * Tq) / 128);
    fused_tc<<<gF, 512, SMEM_BYTES>>>(b_out, qk, out);
}

// round 13
// speedup vs baseline: 1.1467x; 1.1467x over previous
#include <cuda_runtime.h>
#include <cuda_fp16.h>
#include <math.h>

#define Bq 2
#define Dq 256
#define Hq 8
#define Tq 128
#define Fq 64
#define Cq 512
#define TEq 512
#define NDIST 255   // pd in [-127,127]
#define NKQ 4       // tp K-slices

// ---------------- scratch (device globals; no allocation allowed) ----------
__device__ float  g_tpp[NKQ * Bq * Tq * Cq];       // tp partial sums [kq][bt][c]
__device__ float  g_lut[NDIST * Cq];               // dist-emb LUT (255,C)
__device__ __half g_Bn [Cq * Cq];                  // w_out fp16, transposed [n][k]
__device__ __half g_A  [(size_t)Bq * Tq * Tq * Cq]; // fp16(silu(emb))  33 MB

#define TPP_SLICE (Bq * Tq * Cq)                   // 131072 floats per kq slice

// ---------------- fused-kernel smem layout (in halves) ----------------------
#define STAGE_H   (128 * 40)                 // 5120 halves / stage / operand
#define B_BASE_H  (3 * STAGE_H)              // 15360
#define RS_H      (6 * STAGE_H)              // 30720
#define RS_STRIDE 136                        // halves
#define SBO_BYTE  ((RS_H + 128 * RS_STRIDE) * 2)   // 96256
#define SMEM_BYTES (SBO_BYTE + 512)                // 96768
#define QBUF_H    (128 * 72)                 // 9216 halves per qk buffer

// ---------------- helpers ----------------------------------------------------
__device__ __forceinline__ void mma16(float c[4],
                                      const unsigned a[4],
                                      unsigned b0, unsigned b1) {
    asm volatile(
        "mma.sync.aligned.m16n8k16.row.col.f32.f16.f16.f32 "
        "{%0,%1,%2,%3}, {%4,%5,%6,%7}, {%8,%9}, {%0,%1,%2,%3};"
        : "+f"(c[0]), "+f"(c[1]), "+f"(c[2]), "+f"(c[3])
        : "r"(a[0]), "r"(a[1]), "r"(a[2]), "r"(a[3]), "r"(b0), "r"(b1));
}

__device__ __forceinline__ void ldsm4(unsigned r[4], unsigned addr) {
    asm volatile("ldmatrix.sync.aligned.m8n8.x4.shared.b16 {%0,%1,%2,%3}, [%4];"
                 : "=r"(r[0]), "=r"(r[1]), "=r"(r[2]), "=r"(r[3]) : "r"(addr));
}

__device__ __forceinline__ float silu(float x) {
    return x / (1.0f + __expf(-x));
}

__device__ __forceinline__ void cpa16(void* dst, const void* src) {
    unsigned d = (unsigned)__cvta_generic_to_shared(dst);
    asm volatile("cp.async.cg.shared.global [%0], [%1], 16;" :: "r"(d), "l"(src) : "memory");
}

__device__ __forceinline__ void stg_cs_f2(float* p, float x, float y) {
    asm volatile("st.global.cs.v2.f32 [%0], {%1, %2};" :: "l"(p), "f"(x), "f"(y)
                 : "memory");
}

// ---------------- kernel 1: merged prologue ---------------------------------
// blocks [0,255): dist LUT
// blocks [255,319): w_out -> fp16 transposed [n][k] via smem 64x64 tiles
// blocks [319,1343): time_proj partials, block = (bt, kq), 128-k slice
__global__ __launch_bounds__(512) void prep_kernel(const float* __restrict__ w_dist,
                                                   const float* __restrict__ b_dist,
                                                   const float* __restrict__ w_out,
                                                   const float* __restrict__ temb,
                                                   const float* __restrict__ w_time,
                                                   const float* __restrict__ b_time) {
    int blk = blockIdx.x;
    int tid = threadIdx.x;
    if (blk < NDIST) {
        int didx = blk;
        float d  = (float)(didx - (Tq - 1));
        float e0 = log1pf(fmaxf(d, 0.0f));
        float e1 = log1pf(fmaxf(-d, 0.0f));
        float e2 = (didx == (Tq - 1)) ? 1.0f : 0.0f;
        g_lut[didx * Cq + tid] = e0 * w_dist[0 * Cq + tid]
                               + e1 * w_dist[1 * Cq + tid]
                               + e2 * w_dist[2 * Cq + tid]
                               + b_dist[tid];
    } else if (blk < NDIST + 64) {
        __shared__ __half ts[64][65];
        int blk2 = blk - NDIST;               // 0..63
        int k0 = (blk2 >> 3) * 64, n0 = (blk2 & 7) * 64;
        int cl = tid & 63, rbase = tid >> 6;  // 8 rows/pass
        #pragma unroll
        for (int r = 0; r < 8; ++r) {
            int kl = r * 8 + rbase;
            ts[kl][cl] = __float2half(w_out[(size_t)(k0 + kl) * Cq + n0 + cl]);
        }
        __syncthreads();
        #pragma unroll
        for (int r = 0; r < 8; ++r) {
            int nl = r * 8 + rbase;
            g_Bn[(size_t)(n0 + nl) * Cq + k0 + cl] = ts[cl][nl];
        }
    } else {
        __shared__ float st[128];
        int idx = blk - NDIST - 64;           // 0..1023
        int bt = idx >> 2, kq = idx & 3;
        int c  = tid;
        if (tid < 128) st[tid] = temb[(size_t)bt * TEq + kq * 128 + tid];
        __syncthreads();
        float acc = (kq == 0) ? b_time[c] : 0.0f;
        const float* wp = w_time + (size_t)(kq * 128) * Cq + c;
        #pragma unroll 16
        for (int k = 0; k < 128; ++k)
            acc += st[k] * wp[(size_t)k * Cq];
        g_tpp[(size_t)(kq * (Bq * Tq) + bt) * Cq + c] = acc;
    }
}

// ---------------- kernel 2: A = fp16(silu(sum_kq tpp + lut[pd]))  -----------
__global__ __launch_bounds__(256) void act_kernel(const int* __restrict__ pd) {
    int idx    = blockIdx.x * 256 + threadIdx.x;
    int k8     = (idx & 63) * 8;           // 0..504
    int rowidx = idx >> 6;                 // 0..32767  (= bt*128 + s)
    int bt     = rowidx >> 7;
    int didx   = pd[rowidx] + (Tq - 1);
    const float* lp = g_lut + (size_t)didx * Cq + k8;
    const float* tp = g_tpp + (size_t)bt   * Cq + k8;
    float4 t0 = *(const float4*)tp;
    float4 t1 = *(const float4*)(tp + 4);
    #pragma unroll
    for (int kq = 1; kq < NKQ; ++kq) {
        const float* tq = tp + (size_t)kq * TPP_SLICE;
        float4 p0 = *(const float4*)tq;
        float4 p1 = *(const float4*)(tq + 4);
        t0.x += p0.x; t0.y += p0.y; t0.z += p0.z; t0.w += p0.w;
        t1.x += p1.x; t1.y += p1.y; t1.z += p1.z; t1.w += p1.w;
    }
    float4 l0 = *(const float4*)lp;
    float4 l1 = *(const float4*)(lp + 4);
    union { uint4 u; __half2 h[4]; } o;
    o.h[0] = __floats2half2_rn(silu(t0.x + l0.x), silu(t0.y + l0.y));
    o.h[1] = __floats2half2_rn(silu(t0.z + l0.z), silu(t0.w + l0.w));
    o.h[2] = __floats2half2_rn(silu(t1.x + l1.x), silu(t1.y + l1.y));
    o.h[3] = __floats2half2_rn(silu(t1.z + l1.z), silu(t1.w + l1.w));
    *(uint4*)(g_A + (size_t)rowidx * Cq + k8) = o.u;
}

// ---------------- kernel 3: FUSED  R-tile GEMM + einsum (fp16 MMA) ----------
// block = (bn: 128-col chunk of C = 2 heads, bt: one (b,t) pair).
// Phase 1: Rs[128 s][128 f'] = A(bt) @ Bn(bn)^T + bias   (smem, fp16)
//          K-chunk 32, 3-stage cp.async ring, 16 iterations, one sync each.
// Phase 2: for dchunk(2) x hh(2): out[d,s] = qk[d,f] . Rs[s, hh*64+f]
__global__ __launch_bounds__(512, 2) void fused_tc(const float* __restrict__ b_out,
                                                   const float* __restrict__ qk,
                                                   float* __restrict__ out) {
    extern __shared__ __half sm[];
    __half* Rs  = sm + RS_H;
    float*  sbo = (float*)((char*)sm + SBO_BYTE);

    int tid = threadIdx.x;
    int bn = blockIdx.x;           // 0..3
    int bt = blockIdx.y;           // 0..255
    if (tid < 128) sbo[tid] = b_out[bn * 128 + tid];

    // ---------------- phase 1 ------------------------------------------------
    int crow = tid >> 2;           // 0..127
    int cseg = tid & 3;            // 0..3 (16B = 8 halves each)
    const __half* Asrc = g_A  + (size_t)(bt * 128) * Cq + cseg * 8;
    const __half* Bsrc = g_Bn + (size_t)(bn * 128) * Cq + cseg * 8;

    #define ISSUE(stage, kk)                                                      \
        { cpa16(sm + (stage) * STAGE_H + crow * 40 + cseg * 8,                    \
                Asrc + (size_t)(kk) + (size_t)crow * Cq);                         \
          cpa16(sm + B_BASE_H + (stage) * STAGE_H + crow * 40 + cseg * 8,         \
                Bsrc + (size_t)(kk) + (size_t)crow * Cq);                         \
          asm volatile("cp.async.commit_group;" ::: "memory"); }

    ISSUE(0, 0)
    ISSUE(1, 32)
    asm volatile("cp.async.wait_group 1;" ::: "memory");
    __syncthreads();

    int lane = tid & 31, warp = tid >> 5;   // 16 warps
    int g = lane >> 2, tig = lane & 3;
    int wm = warp & 3, wn = warp >> 2;
    int mbase = wm * 32, nbase = wn * 32;

    unsigned aBase = (unsigned)__cvta_generic_to_shared(sm);
    unsigned bBase = (unsigned)__cvta_generic_to_shared(sm + B_BASE_H);
    unsigned rBase = (unsigned)__cvta_generic_to_shared(Rs);
    int rowA   = lane & 15;
    int colA16 = (lane >> 4) * 16;          // bytes
    int rowB   = (lane & 7) | ((lane & 16) >> 1);
    int colB16 = ((lane >> 3) & 1) * 16;    // bytes
    unsigned aAddr[2], bAddr[2];
    #pragma unroll
    for (int mt = 0; mt < 2; ++mt)
        aAddr[mt] = aBase + (mbase + mt * 16 + rowA) * 80 + colA16;
    #pragma unroll
    for (int p = 0; p < 2; ++p)
        bAddr[p] = bBase + (nbase + p * 16 + rowB) * 80 + colB16;

    {
        float acc[2][4][4] = {};
        for (int i = 0; i < 16; ++i) {
            int cur = i % 3;
            if (i + 2 < 16) ISSUE((i + 2) % 3, (i + 2) * 32)
            unsigned bufo = (unsigned)cur * (STAGE_H * 2);
            #pragma unroll
            for (int ks = 0; ks < 2; ++ks) {
                unsigned off = bufo + ks * 32;
                unsigned a0[4], a1[4], bfr[4];
                ldsm4(a0, aAddr[0] + off);
                ldsm4(a1, aAddr[1] + off);
                #pragma unroll
                for (int p = 0; p < 2; ++p) {
                    ldsm4(bfr, bAddr[p] + off);
                    mma16(acc[0][2 * p],     a0, bfr[0], bfr[1]);
                    mma16(acc[0][2 * p + 1], a0, bfr[2], bfr[3]);
                    mma16(acc[1][2 * p],     a1, bfr[0], bfr[1]);
                    mma16(acc[1][2 * p + 1], a1, bfr[2], bfr[3]);
                }
            }
            if (i < 15) {
                if (i + 2 < 16)
                    asm volatile("cp.async.wait_group 1;" ::: "memory");
                else
                    asm volatile("cp.async.wait_group 0;" ::: "memory");
                __syncthreads();
            }
        }
        #undef ISSUE

        // phase-1 epilogue: Rs[s][f'] = fp16(acc + bias)
        #pragma unroll
        for (int mt = 0; mt < 2; ++mt) {
            int r0 = mbase + mt * 16 + g;
            #pragma unroll
            for (int nt = 0; nt < 4; ++nt) {
                int nl = nbase + nt * 8 + 2 * tig;
                *(__half2*)&Rs[r0 * RS_STRIDE + nl] =
                    __floats2half2_rn(acc[mt][nt][0] + sbo[nl],
                                      acc[mt][nt][1] + sbo[nl + 1]);
                *(__half2*)&Rs[(r0 + 8) * RS_STRIDE + nl] =
                    __floats2half2_rn(acc[mt][nt][2] + sbo[nl],
                                      acc[mt][nt][3] + sbo[nl + 1]);
            }
        }
    }
    __syncthreads();   // Rs complete; pipeline smem free for qk buffers

    // ---------------- phase 2 ------------------------------------------------
    int b = bt >> 7, t = bt & 127;
    const size_t dstr = (size_t)Hq * Tq * Fq;   // 65536
    const size_t ostr = (size_t)Hq * Tq * Tq;   // 131072
    __half* Qs = sm;                            // [2][128][72] halves

    unsigned aAddr2[2], bAddr2[2];
    #pragma unroll
    for (int mt = 0; mt < 2; ++mt)
        aAddr2[mt] = aBase + (mbase + mt * 16 + rowA) * 144 + colA16;
    #pragma unroll
    for (int p = 0; p < 2; ++p)
        bAddr2[p] = rBase + (nbase + p * 16 + rowB) * 272 + colB16;

    // prologue: load qk tile for iter 0 (dchunk 0, head 2*bn)
    float4 qv[4];
    {
        const float* qp = qk + ((((size_t)b * Dq) * Hq + 2 * bn) * Tq + t) * Fq;
        #pragma unroll
        for (int r = 0; r < 4; ++r) {
            int idx = tid + r * 512;
            int row = idx >> 4, f4 = (idx & 15) * 4;
            qv[r] = *(const float4*)(qp + (size_t)row * dstr + f4);
        }
        #pragma unroll
        for (int r = 0; r < 4; ++r) {
            int idx = tid + r * 512;
            int row = idx >> 4, f4 = (idx & 15) * 4;
            union { uint2 u; __half2 h[2]; } o;
            o.h[0] = __floats2half2_rn(qv[r].x, qv[r].y);
            o.h[1] = __floats2half2_rn(qv[r].z, qv[r].w);
            *(uint2*)&Qs[row * 72 + f4] = o.u;
        }
    }
    __syncthreads();

    #pragma unroll
    for (int iter = 0; iter < 4; ++iter) {
        int cur = iter & 1;
        int dchunk = iter >> 1, hh = iter & 1;
        if (iter < 3) {
            int ni = iter + 1;
            const float* qp = qk + ((((size_t)b * Dq + (ni >> 1) * 128) * Hq
                                     + 2 * bn + (ni & 1)) * Tq + t) * Fq;
            #pragma unroll
            for (int r = 0; r < 4; ++r) {
                int idx = tid + r * 512;
                int row = idx >> 4, f4 = (idx & 15) * 4;
                qv[r] = *(const float4*)(qp + (size_t)row * dstr + f4);
            }
        }
        float acc2[2][4][4] = {};
        unsigned qoff = (unsigned)cur * (QBUF_H * 2);
        unsigned roff = (unsigned)hh * 128;          // hh*64 halves (bytes)
        #pragma unroll
        for (int ks = 0; ks < 4; ++ks) {
            unsigned off = ks * 32;
            unsigned a0[4], a1[4], bfr[4];
            ldsm4(a0, aAddr2[0] + qoff + off);
            ldsm4(a1, aAddr2[1] + qoff + off);
            #pragma unroll
            for (int p = 0; p < 2; ++p) {
                ldsm4(bfr, bAddr2[p] + roff + off);
                mma16(acc2[0][2 * p],     a0, bfr[0], bfr[1]);
                mma16(acc2[0][2 * p + 1], a0, bfr[2], bfr[3]);
                mma16(acc2[1][2 * p],     a1, bfr[0], bfr[1]);
                mma16(acc2[1][2 * p + 1], a1, bfr[2], bfr[3]);
            }
        }
        float* ob = out + ((((size_t)b * Dq + dchunk * 128) * Hq
                            + 2 * bn + hh) * Tq + t) * Tq;
        #pragma unroll
        for (int mt = 0; mt < 2; ++mt) {
            int r0 = mbase + mt * 16 + g;
            #pragma unroll
            for (int nt = 0; nt < 4; ++nt) {
                int nl = nbase + nt * 8 + 2 * tig;
                stg_cs_f2(ob + (size_t)r0 * ostr + nl,
                          acc2[mt][nt][0], acc2[mt][nt][1]);
                stg_cs_f2(ob + (size_t)(r0 + 8) * ostr + nl,
                          acc2[mt][nt][2], acc2[mt][nt][3]);
            }
        }
        if (iter < 3) {
            #pragma unroll
            for (int r = 0; r < 4; ++r) {
                int idx = tid + r * 512;
                int row = idx >> 4, f4 = (idx & 15) * 4;
                union { uint2 u; __half2 h[2]; } o;
                o.h[0] = __floats2half2_rn(qv[r].x, qv[r].y);
                o.h[1] = __floats2half2_rn(qv[r].z, qv[r].w);
                *(uint2*)&Qs[(cur ^ 1) * QBUF_H + row * 72 + f4] = o.u;
            }
            __syncthreads();
        }
    }
}

// ---------------------------------------------------------------------------
extern "C" void kernel_launch(void* const* d_in, const int* in_sizes, int n_in,
                              void* d_out, int out_size) {
    const float* qk     = (const float*)d_in[0];
    const float* temb   = (const float*)d_in[1];
    const int*   pd     = (const int*)  d_in[2];
    const float* w_dist = (const float*)d_in[3];
    const float* b_dist = (const float*)d_in[4];
    const float* w_time = (const float*)d_in[5];
    const float* b_time = (const float*)d_in[6];
    const float* w_out  = (const float*)d_in[7];
    const float* b_out  = (const float*)d_in[8];
    float* out = (float*)d_out;

    static int smem_set = 0;
    if (!smem_set) {
        cudaFuncSetAttribute(fused_tc, cudaFuncAttributeMaxDynamicSharedMemorySize,
                             SMEM_BYTES);
        smem_set = 1;
    }

    prep_kernel<<<NDIST + 64 + NKQ * Bq * Tq, 512>>>(w_dist, b_dist, w_out,
                                                     temb, w_time, b_time);
    act_kernel<<<(Bq * Tq * Tq * Cq / 8) / 256, 256>>>(pd);
    dim3 gF(Cq / 128, (Bq * Tq * Tq) / 128);
    fused_tc<<<gF, 512, SMEM_BYTES>>>(b_out, qk, out);
}

// round 14
// speedup vs baseline: 1.1718x; 1.0219x over previous
#include <cuda_runtime.h>
#include <cuda_fp16.h>
#include <math.h>

#define Bq 2
#define Dq 256
#define Hq 8
#define Tq 128
#define Fq 64
#define Cq 512
#define TEq 512
#define NDIST 255   // pd in [-127,127]
#define NKQ 4       // tp K-slices

// ---------------- scratch (device globals; no allocation allowed) ----------
__device__ float  g_tpp[NKQ * Bq * Tq * Cq];       // tp partial sums [kq][bt][c]
__device__ float  g_tp [Bq * Tq * Cq];             // reduced time projection
__device__ float  g_lut[NDIST * Cq];               // dist-emb LUT (255,C)
__device__ __half g_Bn [Cq * Cq];                  // w_out fp16, transposed [n][k]
__device__ __half g_A  [(size_t)Bq * Tq * Tq * Cq]; // fp16(silu(emb))  33 MB

#define TPP_SLICE (Bq * Tq * Cq)                   // 131072 floats per kq slice

// ---------------- fused-kernel smem layout (in halves) ----------------------
#define STAGE_H   (128 * 40)                 // 5120 halves / stage / operand
#define B_BASE_H  (3 * STAGE_H)              // 15360
#define RS_H      (6 * STAGE_H)              // 30720
#define RS_STRIDE 136                        // halves
#define SBO_BYTE  ((RS_H + 128 * RS_STRIDE) * 2)   // 96256
#define SMEM_BYTES (SBO_BYTE + 512)                // 96768
#define QBUF_H    (128 * 72)                 // 9216 halves per qk buffer

// ---------------- helpers ----------------------------------------------------
__device__ __forceinline__ void mma16(float c[4],
                                      const unsigned a[4],
                                      unsigned b0, unsigned b1) {
    asm volatile(
        "mma.sync.aligned.m16n8k16.row.col.f32.f16.f16.f32 "
        "{%0,%1,%2,%3}, {%4,%5,%6,%7}, {%8,%9}, {%0,%1,%2,%3};"
        : "+f"(c[0]), "+f"(c[1]), "+f"(c[2]), "+f"(c[3])
        : "r"(a[0]), "r"(a[1]), "r"(a[2]), "r"(a[3]), "r"(b0), "r"(b1));
}

__device__ __forceinline__ void ldsm4(unsigned r[4], unsigned addr) {
    asm volatile("ldmatrix.sync.aligned.m8n8.x4.shared.b16 {%0,%1,%2,%3}, [%4];"
                 : "=r"(r[0]), "=r"(r[1]), "=r"(r[2]), "=r"(r[3]) : "r"(addr));
}

__device__ __forceinline__ float silu(float x) {
    return x / (1.0f + __expf(-x));
}

__device__ __forceinline__ void cpa16(void* dst, const void* src) {
    unsigned d = (unsigned)__cvta_generic_to_shared(dst);
    asm volatile("cp.async.cg.shared.global [%0], [%1], 16;" :: "r"(d), "l"(src) : "memory");
}

__device__ __forceinline__ void stg_cs_f2(float* p, float x, float y) {
    asm volatile("st.global.cs.v2.f32 [%0], {%1, %2};" :: "l"(p), "f"(x), "f"(y)
                 : "memory");
}

// ---------------- kernel 1: merged prologue ---------------------------------
// blocks [0,255): dist LUT
// blocks [255,319): w_out -> fp16 transposed [n][k] via smem 64x64 tiles
// blocks [319,447): time_proj partials, block = (btg of 8 bt, kq), 128-k slice
__global__ __launch_bounds__(512) void prep_kernel(const float* __restrict__ w_dist,
                                                   const float* __restrict__ b_dist,
                                                   const float* __restrict__ w_out,
                                                   const float* __restrict__ temb,
                                                   const float* __restrict__ w_time,
                                                   const float* __restrict__ b_time) {
    int blk = blockIdx.x;
    int tid = threadIdx.x;
    if (blk < NDIST) {
        int didx = blk;
        float d  = (float)(didx - (Tq - 1));
        float e0 = log1pf(fmaxf(d, 0.0f));
        float e1 = log1pf(fmaxf(-d, 0.0f));
        float e2 = (didx == (Tq - 1)) ? 1.0f : 0.0f;
        g_lut[didx * Cq + tid] = e0 * w_dist[0 * Cq + tid]
                               + e1 * w_dist[1 * Cq + tid]
                               + e2 * w_dist[2 * Cq + tid]
                               + b_dist[tid];
    } else if (blk < NDIST + 64) {
        __shared__ __half ts[64][65];
        int blk2 = blk - NDIST;               // 0..63
        int k0 = (blk2 >> 3) * 64, n0 = (blk2 & 7) * 64;
        int cl = tid & 63, rbase = tid >> 6;  // 8 rows/pass
        #pragma unroll
        for (int r = 0; r < 8; ++r) {
            int kl = r * 8 + rbase;
            ts[kl][cl] = __float2half(w_out[(size_t)(k0 + kl) * Cq + n0 + cl]);
        }
        __syncthreads();
        #pragma unroll
        for (int r = 0; r < 8; ++r) {
            int nl = r * 8 + rbase;
            g_Bn[(size_t)(n0 + nl) * Cq + k0 + cl] = ts[cl][nl];
        }
    } else {
        __shared__ float st[8][128];
        int idx = blk - NDIST - 64;           // 0..127
        int btg = idx >> 2, kq = idx & 3;
        int bt0 = btg * 8;
        int c   = tid;
        #pragma unroll
        for (int j = 0; j < 2; ++j) {
            int e = tid + j * 512;            // 0..1023
            int row = e >> 7, kk = e & 127;
            st[row][kk] = temb[(size_t)(bt0 + row) * TEq + kq * 128 + kk];
        }
        __syncthreads();
        float acc[8];
        float bias = (kq == 0) ? b_time[c] : 0.0f;
        #pragma unroll
        for (int r = 0; r < 8; ++r) acc[r] = bias;
        const float* wp = w_time + (size_t)(kq * 128) * Cq + c;
        #pragma unroll 8
        for (int k = 0; k < 128; ++k) {
            float w = wp[(size_t)k * Cq];
            #pragma unroll
            for (int r = 0; r < 8; ++r)
                acc[r] += st[r][k] * w;
        }
        #pragma unroll
        for (int r = 0; r < 8; ++r)
            g_tpp[(size_t)(kq * (Bq * Tq) + bt0 + r) * Cq + c] = acc[r];
    }
}

// ---------------- kernel 1b: reduce tp partials ------------------------------
__global__ __launch_bounds__(512) void reduce_tp(int dummy) {
    int bt = blockIdx.x, c = threadIdx.x;
    float s = 0.0f;
    #pragma unroll
    for (int kq = 0; kq < NKQ; ++kq)
        s += g_tpp[(size_t)(kq * (Bq * Tq) + bt) * Cq + c];
    g_tp[(size_t)bt * Cq + c] = s;
}

// ---------------- kernel 2: A = fp16(silu(tp + lut[pd]))  -------------------
__global__ __launch_bounds__(256) void act_kernel(const int* __restrict__ pd) {
    int idx    = blockIdx.x * 256 + threadIdx.x;
    int k8     = (idx & 63) * 8;           // 0..504
    int rowidx = idx >> 6;                 // 0..32767  (= bt*128 + s)
    int bt     = rowidx >> 7;
    int didx   = pd[rowidx] + (Tq - 1);
    const float* lp = g_lut + (size_t)didx * Cq + k8;
    const float* tp = g_tp  + (size_t)bt   * Cq + k8;
    float4 t0 = *(const float4*)tp;
    float4 t1 = *(const float4*)(tp + 4);
    float4 l0 = *(const float4*)lp;
    float4 l1 = *(const float4*)(lp + 4);
    union { uint4 u; __half2 h[4]; } o;
    o.h[0] = __floats2half2_rn(silu(t0.x + l0.x), silu(t0.y + l0.y));
    o.h[1] = __floats2half2_rn(silu(t0.z + l0.z), silu(t0.w + l0.w));
    o.h[2] = __floats2half2_rn(silu(t1.x + l1.x), silu(t1.y + l1.y));
    o.h[3] = __floats2half2_rn(silu(t1.z + l1.z), silu(t1.w + l1.w));
    *(uint4*)(g_A + (size_t)rowidx * Cq + k8) = o.u;
}

// ---------------- kernel 3: FUSED  R-tile GEMM + einsum (fp16 MMA) ----------
// block = (bn: 128-col chunk of C = 2 heads, bt: one (b,t) pair).
// Phase 1: Rs[128 s][128 f'] = A(bt) @ Bn(bn)^T + bias   (smem, fp16)
//          K-chunk 32, 3-stage cp.async ring, 16 iterations, one sync each.
// Phase 2: for dchunk(2) x hh(2): out[d,s] = qk[d,f] . Rs[s, hh*64+f]
__global__ __launch_bounds__(512, 2) void fused_tc(const float* __restrict__ b_out,
                                                   const float* __restrict__ qk,
                                                   float* __restrict__ out) {
    extern __shared__ __half sm[];
    __half* Rs  = sm + RS_H;
    float*  sbo = (float*)((char*)sm + SBO_BYTE);

    int tid = threadIdx.x;
    int bn = blockIdx.x;           // 0..3
    int bt = blockIdx.y;           // 0..255
    if (tid < 128) sbo[tid] = b_out[bn * 128 + tid];

    // ---------------- phase 1 ------------------------------------------------
    int crow = tid >> 2;           // 0..127
    int cseg = tid & 3;            // 0..3 (16B = 8 halves each)
    const __half* Asrc = g_A  + (size_t)(bt * 128) * Cq + cseg * 8;
    const __half* Bsrc = g_Bn + (size_t)(bn * 128) * Cq + cseg * 8;

    #define ISSUE(stage, kk)                                                      \
        { cpa16(sm + (stage) * STAGE_H + crow * 40 + cseg * 8,                    \
                Asrc + (size_t)(kk) + (size_t)crow * Cq);                         \
          cpa16(sm + B_BASE_H + (stage) * STAGE_H + crow * 40 + cseg * 8,         \
                Bsrc + (size_t)(kk) + (size_t)crow * Cq);                         \
          asm volatile("cp.async.commit_group;" ::: "memory"); }

    ISSUE(0, 0)
    ISSUE(1, 32)
    asm volatile("cp.async.wait_group 1;" ::: "memory");
    __syncthreads();

    int lane = tid & 31, warp = tid >> 5;   // 16 warps
    int g = lane >> 2, tig = lane & 3;
    int wm = warp & 3, wn = warp >> 2;
    int mbase = wm * 32, nbase = wn * 32;

    unsigned aBase = (unsigned)__cvta_generic_to_shared(sm);
    unsigned bBase = (unsigned)__cvta_generic_to_shared(sm + B_BASE_H);
    unsigned rBase = (unsigned)__cvta_generic_to_shared(Rs);
    int rowA   = lane & 15;
    int colA16 = (lane >> 4) * 16;          // bytes
    int rowB   = (lane & 7) | ((lane & 16) >> 1);
    int colB16 = ((lane >> 3) & 1) * 16;    // bytes
    unsigned aAddr[2], bAddr[2];
    #pragma unroll
    for (int mt = 0; mt < 2; ++mt)
        aAddr[mt] = aBase + (mbase + mt * 16 + rowA) * 80 + colA16;
    #pragma unroll
    for (int p = 0; p < 2; ++p)
        bAddr[p] = bBase + (nbase + p * 16 + rowB) * 80 + colB16;

    {
        float acc[2][4][4] = {};
        for (int i = 0; i < 16; ++i) {
            int cur = i % 3;
            if (i + 2 < 16) ISSUE((i + 2) % 3, (i + 2) * 32)
            unsigned bufo = (unsigned)cur * (STAGE_H * 2);
            #pragma unroll
            for (int ks = 0; ks < 2; ++ks) {
                unsigned off = bufo + ks * 32;
                unsigned a0[4], a1[4], bfr[4];
                ldsm4(a0, aAddr[0] + off);
                ldsm4(a1, aAddr[1] + off);
                #pragma unroll
                for (int p = 0; p < 2; ++p) {
                    ldsm4(bfr, bAddr[p] + off);
                    mma16(acc[0][2 * p],     a0, bfr[0], bfr[1]);
                    mma16(acc[0][2 * p + 1], a0, bfr[2], bfr[3]);
                    mma16(acc[1][2 * p],     a1, bfr[0], bfr[1]);
                    mma16(acc[1][2 * p + 1], a1, bfr[2], bfr[3]);
                }
            }
            if (i < 15) {
                if (i + 2 < 16)
                    asm volatile("cp.async.wait_group 1;" ::: "memory");
                else
                    asm volatile("cp.async.wait_group 0;" ::: "memory");
                __syncthreads();
            }
        }
        #undef ISSUE

        // phase-1 epilogue: Rs[s][f'] = fp16(acc + bias)
        #pragma unroll
        for (int mt = 0; mt < 2; ++mt) {
            int r0 = mbase + mt * 16 + g;
            #pragma unroll
            for (int nt = 0; nt < 4; ++nt) {
                int nl = nbase + nt * 8 + 2 * tig;
                *(__half2*)&Rs[r0 * RS_STRIDE + nl] =
                    __floats2half2_rn(acc[mt][nt][0] + sbo[nl],
                                      acc[mt][nt][1] + sbo[nl + 1]);
                *(__half2*)&Rs[(r0 + 8) * RS_STRIDE + nl] =
                    __floats2half2_rn(acc[mt][nt][2] + sbo[nl],
                                      acc[mt][nt][3] + sbo[nl + 1]);
            }
        }
    }
    __syncthreads();   // Rs complete; pipeline smem free for qk buffers

    // ---------------- phase 2 ------------------------------------------------
    int b = bt >> 7, t = bt & 127;
    const size_t dstr = (size_t)Hq * Tq * Fq;   // 65536
    const size_t ostr = (size_t)Hq * Tq * Tq;   // 131072
    __half* Qs = sm;                            // [2][128][72] halves

    unsigned aAddr2[2], bAddr2[2];
    #pragma unroll
    for (int mt = 0; mt < 2; ++mt)
        aAddr2[mt] = aBase + (mbase + mt * 16 + rowA) * 144 + colA16;
    #pragma unroll
    for (int p = 0; p < 2; ++p)
        bAddr2[p] = rBase + (nbase + p * 16 + rowB) * 272 + colB16;

    // prologue: load qk tile for iter 0 (dchunk 0, head 2*bn)
    float4 qv[4];
    {
        const float* qp = qk + ((((size_t)b * Dq) * Hq + 2 * bn) * Tq + t) * Fq;
        #pragma unroll
        for (int r = 0; r < 4; ++r) {
            int idx = tid + r * 512;
            int row = idx >> 4, f4 = (idx & 15) * 4;
            qv[r] = *(const float4*)(qp + (size_t)row * dstr + f4);
        }
        #pragma unroll
        for (int r = 0; r < 4; ++r) {
            int idx = tid + r * 512;
            int row = idx >> 4, f4 = (idx & 15) * 4;
            union { uint2 u; __half2 h[2]; } o;
            o.h[0] = __floats2half2_rn(qv[r].x, qv[r].y);
            o.h[1] = __floats2half2_rn(qv[r].z, qv[r].w);
            *(uint2*)&Qs[row * 72 + f4] = o.u;
        }
    }
    __syncthreads();

    #pragma unroll
    for (int iter = 0; iter < 4; ++iter) {
        int cur = iter & 1;
        int dchunk = iter >> 1, hh = iter & 1;
        if (iter < 3) {
            int ni = iter + 1;
            const float* qp = qk + ((((size_t)b * Dq + (ni >> 1) * 128) * Hq
                                     + 2 * bn + (ni & 1)) * Tq + t) * Fq;
            #pragma unroll
            for (int r = 0; r < 4; ++r) {
                int idx = tid + r * 512;
                int row = idx >> 4, f4 = (idx & 15) * 4;
                qv[r] = *(const float4*)(qp + (size_t)row * dstr + f4);
            }
        }
        float acc2[2][4][4] = {};
        unsigned qoff = (unsigned)cur * (QBUF_H * 2);
        unsigned roff = (unsigned)hh * 128;          // hh*64 halves (bytes)
        #pragma unroll
        for (int ks = 0; ks < 4; ++ks) {
            unsigned off = ks * 32;
            unsigned a0[4], a1[4], bfr[4];
            ldsm4(a0, aAddr2[0] + qoff + off);
            ldsm4(a1, aAddr2[1] + qoff + off);
            #pragma unroll
            for (int p = 0; p < 2; ++p) {
                ldsm4(bfr, bAddr2[p] + roff + off);
                mma16(acc2[0][2 * p],     a0, bfr[0], bfr[1]);
                mma16(acc2[0][2 * p + 1], a0, bfr[2], bfr[3]);
                mma16(acc2[1][2 * p],     a1, bfr[0], bfr[1]);
                mma16(acc2[1][2 * p + 1], a1, bfr[2], bfr[3]);
            }
        }
        float* ob = out + ((((size_t)b * Dq + dchunk * 128) * Hq
                            + 2 * bn + hh) * Tq + t) * Tq;
        #pragma unroll
        for (int mt = 0; mt < 2; ++mt) {
            int r0 = mbase + mt * 16 + g;
            #pragma unroll
            for (int nt = 0; nt < 4; ++nt) {
                int nl = nbase + nt * 8 + 2 * tig;
                stg_cs_f2(ob + (size_t)r0 * ostr + nl,
                          acc2[mt][nt][0], acc2[mt][nt][1]);
                stg_cs_f2(ob + (size_t)(r0 + 8) * ostr + nl,
                          acc2[mt][nt][2], acc2[mt][nt][3]);
            }
        }
        if (iter < 3) {
            #pragma unroll
            for (int r = 0; r < 4; ++r) {
                int idx = tid + r * 512;
                int row = idx >> 4, f4 = (idx & 15) * 4;
                union { uint2 u; __half2 h[2]; } o;
                o.h[0] = __floats2half2_rn(qv[r].x, qv[r].y);
                o.h[1] = __floats2half2_rn(qv[r].z, qv[r].w);
                *(uint2*)&Qs[(cur ^ 1) * QBUF_H + row * 72 + f4] = o.u;
            }
            __syncthreads();
        }
    }
}

// ---------------------------------------------------------------------------
extern "C" void kernel_launch(void* const* d_in, const int* in_sizes, int n_in,
                              void* d_out, int out_size) {
    const float* qk     = (const float*)d_in[0];
    const float* temb   = (const float*)d_in[1];
    const int*   pd     = (const int*)  d_in[2];
    const float* w_dist = (const float*)d_in[3];
    const float* b_dist = (const float*)d_in[4];
    const float* w_time = (const float*)d_in[5];
    const float* b_time = (const float*)d_in[6];
    const float* w_out  = (const float*)d_in[7];
    const float* b_out  = (const float*)d_in[8];
    float* out = (float*)d_out;

    static int smem_set = 0;
    if (!smem_set) {
        cudaFuncSetAttribute(fused_tc, cudaFuncAttributeMaxDynamicSharedMemorySize,
                             SMEM_BYTES);
        smem_set = 1;
    }

    prep_kernel<<<NDIST + 64 + (Bq * Tq / 8) * NKQ, 512>>>(w_dist, b_dist, w_out,
                                                           temb, w_time, b_time);
    reduce_tp<<<Bq * Tq, Cq>>>(0);
    act_kernel<<<(Bq * Tq * Tq * Cq / 8) / 256, 256>>>(pd);
    dim3 gF(Cq / 128, (Bq * Tq * Tq) / 128);
    fused_tc<<<gF, 512, SMEM_BYTES>>>(b_out, qk, out);
}